// round 15
// baseline (speedup 1.0000x reference)
#include <cuda_runtime.h>
#include <cuda_bf16.h>
#include <cstddef>
#include <stdint.h>
#include <math.h>

// Problem dims (fixed)
#define BB   8
#define NN   2048
#define DD   1024
#define H1   128
#define FF   28
#define DK   64
#define MM   (BB*NN)        // 16384
#define NSTEPS 4

// ---------------- scratch (static device arrays) -------------
__device__ float g_h[MM * H1];
__device__ float g_Q[MM * DK];
__device__ float g_K[MM * DK];
__device__ float g_V[MM * DK];
__device__ float g_VT[(size_t)BB * DK * NN];
__device__ float g_charge[MM];
__device__ float g_chist[4 * MM];
__device__ float g_recv[MM];                      // zero-invariant between launches
__device__ float g_rowinv[MM];
__device__ float g_out64[MM * DK];
__device__ float g_compat[(size_t)BB * NN * NN];  // 134 MB; lower triangle valid

// bf16 split operands
__device__ __nv_bfloat16 g_hs_hi[(size_t)MM * DD];
__device__ __nv_bfloat16 g_hs_lo[(size_t)MM * DD];
__device__ __nv_bfloat16 g_w1_hi[H1 * DD];
__device__ __nv_bfloat16 g_w1_lo[H1 * DD];
__device__ __nv_bfloat16 g_wv_hi[DK * DD];
__device__ __nv_bfloat16 g_wv_lo[DK * DD];
__device__ __nv_bfloat16 g_wo_hi[DD * DK];
__device__ __nv_bfloat16 g_wo_lo[DD * DK];
__device__ __nv_bfloat16 g_Q_hi[MM * DK];
__device__ __nv_bfloat16 g_Q_lo[MM * DK];
__device__ __nv_bfloat16 g_K_hi[MM * DK];
__device__ __nv_bfloat16 g_K_lo[MM * DK];
__device__ __nv_bfloat16 g_o64_hi[MM * DK];
__device__ __nv_bfloat16 g_o64_lo[MM * DK];

#define EPI_NONE       0
#define EPI_GELU_BIAS  1
#define EPI_ALPHA      2
#define EPI_SCALE      3

// ---------------- warp-level bf16 MMA (sm_80+ baseline PTX, no 'a' features) --------
__device__ __forceinline__ void mma16816(float* d, const uint32_t* a, const uint32_t* b)
{
    asm volatile(
        "mma.sync.aligned.m16n8k16.row.col.f32.bf16.bf16.f32 "
        "{%0,%1,%2,%3}, {%4,%5,%6,%7}, {%8,%9}, {%0,%1,%2,%3};"
        : "+f"(d[0]), "+f"(d[1]), "+f"(d[2]), "+f"(d[3])
        : "r"(a[0]), "r"(a[1]), "r"(a[2]), "r"(a[3]), "r"(b[0]), "r"(b[1]));
}

// smem tile geometry: rows padded to 72 bf16 (144 B) -> fragment loads bank-conflict-free
#define AP        72
#define A_BYTES   (128 * AP * 2)            // 18432
#define B_BYTES   (64 * AP * 2)             // 9216
#define BUF_BYTES (A_BYTES + B_BYTES)       // 27648
#define G_SMEM    (2 * BUF_BYTES)           // 55296

// ============ tensor GEMM: C[M,N] = epi( A[M,K] @ B[N,K]^T ), split-bf16 3-term ======
// A' = [Ahi, Ahi, Alo], B' = [Bhi, Blo, Bhi] along K (K' = 3K).  nC = 3K/64 chunks.
// 128x64 block tile, 8 warps of 32x32; m16n8k16 fragments via documented thread maps.
template<int EPI, bool TRI>
__global__ __launch_bounds__(256)
void mma_gemm_kernel(const __nv_bfloat16* __restrict__ Ahi, const __nv_bfloat16* __restrict__ Alo,
                     const __nv_bfloat16* __restrict__ Bhi, const __nv_bfloat16* __restrict__ Blo,
                     const float* __restrict__ bias, float* __restrict__ C,
                     int N, int K, size_t sA, size_t sB, size_t sC,
                     const float* __restrict__ alpha_ptr)
{
    const int bz = blockIdx.z;
    const int bn = blockIdx.x * 64;
    const int bm = blockIdx.y * 128;
    if (TRI && bn >= bm + 128) return;

    extern __shared__ char dsm[];
    const int t = threadIdx.x;
    const int warp = t >> 5, lane = t & 31;
    const int g = lane >> 2, tg = lane & 3;
    const int wm = warp >> 1, wn = warp & 1;      // 4 x 2 warp grid

    const __nv_bfloat16* Ah = Ahi + (size_t)bz * sA;
    const __nv_bfloat16* Al = Alo + (size_t)bz * sA;
    const __nv_bfloat16* Bh = Bhi + (size_t)bz * sB;
    const __nv_bfloat16* Bl = Blo + (size_t)bz * sB;

    const int nCps = K / 64;
    const int nC = 3 * nCps;

    // global->smem loader mapping
    const int arow = t >> 1, acb = (t & 1) * 32;   // A: 2 thr/row, 32 cols each
    const int brow = t >> 2, bcb = (t & 3) * 16;   // B: 4 thr/row, 16 cols each

    auto load_tile = [&](int c, int buf) {
        const int seg = c / nCps;
        const int k0 = (c - seg * nCps) * 64;
        const __nv_bfloat16* sAp = (seg == 2) ? Al : Ah;
        const __nv_bfloat16* sBp = (seg == 1) ? Bl : Bh;
        __nv_bfloat16* As = (__nv_bfloat16*)(dsm + buf * BUF_BYTES);
        __nv_bfloat16* Bs = (__nv_bfloat16*)(dsm + buf * BUF_BYTES + A_BYTES);
        const __nv_bfloat16* srcA = sAp + (size_t)(bm + arow) * K + k0 + acb;
#pragma unroll
        for (int q = 0; q < 8; q++)
            *(uint2*)(As + arow * AP + acb + q * 4) = *(const uint2*)(srcA + q * 4);
        const __nv_bfloat16* srcB = sBp + (size_t)(bn + brow) * K + k0 + bcb;
#pragma unroll
        for (int q = 0; q < 4; q++)
            *(uint2*)(Bs + brow * AP + bcb + q * 4) = *(const uint2*)(srcB + q * 4);
    };

    float acc[2][4][4];
#pragma unroll
    for (int mt = 0; mt < 2; mt++)
#pragma unroll
        for (int nt = 0; nt < 4; nt++)
#pragma unroll
            for (int q = 0; q < 4; q++) acc[mt][nt][q] = 0.f;

    load_tile(0, 0);
    __syncthreads();

    for (int c = 0; c < nC; c++) {
        const int buf = c & 1;
        if (c + 1 < nC) load_tile(c + 1, buf ^ 1);

        const uint32_t* Asw = (const uint32_t*)(dsm + buf * BUF_BYTES);
        const uint32_t* Bsw = (const uint32_t*)(dsm + buf * BUF_BYTES + A_BYTES);
        // word pitch = AP/2 = 36
#pragma unroll
        for (int ks = 0; ks < 4; ks++) {
            const int kw = ks * 8;                 // k16 step -> 8 words
            uint32_t af[2][4];
#pragma unroll
            for (int mt = 0; mt < 2; mt++) {
                int rb = wm * 32 + mt * 16;
                int base = (rb + g) * 36 + kw + tg;
                af[mt][0] = Asw[base];
                af[mt][1] = Asw[base + 8 * 36];
                af[mt][2] = Asw[base + 4];
                af[mt][3] = Asw[base + 8 * 36 + 4];
            }
            uint32_t bfr[4][2];
#pragma unroll
            for (int nt = 0; nt < 4; nt++) {
                int nb = wn * 32 + nt * 8;
                int base = (nb + g) * 36 + kw + tg;
                bfr[nt][0] = Bsw[base];
                bfr[nt][1] = Bsw[base + 4];
            }
#pragma unroll
            for (int mt = 0; mt < 2; mt++)
#pragma unroll
                for (int nt = 0; nt < 4; nt++)
                    mma16816(acc[mt][nt], af[mt], bfr[nt]);
        }
        __syncthreads();
    }

    // ---- epilogue ----
    float alpha = 1.f;
    if (EPI == EPI_ALPHA) alpha = 0.2f / (1.f + expf(-(*alpha_ptr)));
    float* Cb = C + (size_t)bz * sC;

#pragma unroll
    for (int mt = 0; mt < 2; mt++) {
#pragma unroll
        for (int nt = 0; nt < 4; nt++) {
            int col = bn + wn * 32 + nt * 8 + tg * 2;
#pragma unroll
            for (int half = 0; half < 2; half++) {
                int row = bm + wm * 32 + mt * 16 + g + half * 8;
                float x0 = acc[mt][nt][half * 2 + 0];
                float x1 = acc[mt][nt][half * 2 + 1];
                if (EPI == EPI_GELU_BIAS) {
                    x0 += bias[col];     x0 = 0.5f * x0 * (1.f + erff(x0 * 0.70710678118654752f));
                    x1 += bias[col + 1]; x1 = 0.5f * x1 * (1.f + erff(x1 * 0.70710678118654752f));
                }
                if (EPI == EPI_ALPHA) { x0 *= alpha; x1 *= alpha; }
                if (EPI == EPI_SCALE) { x0 *= 0.125f; x1 *= 0.125f; }
                float2 v; v.x = x0; v.y = x1;
                *(float2*)(Cb + (size_t)row * N + col) = v;
            }
        }
    }
}

// ---------------- fp32 -> (hi, lo) bf16 split conversions -----------------
__global__ void cvt_split_kernel(const float* __restrict__ s,
                                 __nv_bfloat16* __restrict__ hi,
                                 __nv_bfloat16* __restrict__ lo, int n)
{
    int i = blockIdx.x * 256 + threadIdx.x;
    if (i < n) {
        float v = s[i];
        __nv_bfloat16 h = __float2bfloat16(v);
        hi[i] = h;
        lo[i] = __float2bfloat16(v - __bfloat162float(h));
    }
}
__global__ void cvt_split_qk_kernel()
{
    int i = blockIdx.x * 256 + threadIdx.x;
    float q = g_Q[i];
    __nv_bfloat16 qh = __float2bfloat16(q);
    g_Q_hi[i] = qh;
    g_Q_lo[i] = __float2bfloat16(q - __bfloat162float(qh));
    float k = g_K[i];
    __nv_bfloat16 kh = __float2bfloat16(k);
    g_K_hi[i] = kh;
    g_K_lo[i] = __float2bfloat16(k - __bfloat162float(kh));
}
__global__ void cvt_split_o64_kernel()
{
    int i = blockIdx.x * 256 + threadIdx.x;
    float v = g_out64[i];
    __nv_bfloat16 h = __float2bfloat16(v);
    g_o64_hi[i] = h;
    g_o64_lo[i] = __float2bfloat16(v - __bfloat162float(h));
}

// ============== fused attn@V: out64 += (exp(compat*m)*rowinv) @ VT, split-K ==========
#define TBM 128
#define TBN 64
#define TBK 16
__global__ __launch_bounds__(256)
void attn_v_fused_kernel(const float* __restrict__ step_ptr)
{
    const int b = blockIdx.z;
    const int ks = blockIdx.x;             // k-slice 0..3 (512 cols each)
    const int bm = blockIdx.y * TBM;

    const int cps = 512 / TBK;             // 32 chunks per slice
    int kmax = min(NN, bm + TBM);
    int c0 = ks * cps;
    int c1 = min(kmax / TBK, (ks + 1) * cps);
    if (c0 >= c1) return;

    __shared__ float As[2][TBK][TBM + 4];
    __shared__ float Bs[2][TBK][TBN + 4];
    __shared__ float chs_s[4][512];
    __shared__ float acoef[4][TBM];
    __shared__ float rinv_s[TBM];

    const float step = *step_ptr;
    const float* Cb  = g_compat + (size_t)b * NN * NN;
    const float* VTb = g_VT + (size_t)b * DK * NN;

    const int t = threadIdx.x;
    const int jbase = ks * 512;
    for (int idx = t; idx < 4 * 512; idx += 256) {
        int s = idx >> 9, j = idx & 511;
        chs_s[s][j] = g_chist[s * MM + b * NN + jbase + j];
    }
    for (int idx = t; idx < TBM; idx += 256) {
        int r = b * NN + bm + idx;
        rinv_s[idx] = g_rowinv[r];
        acoef[0][idx] = step * g_chist[0 * MM + r];
        acoef[1][idx] = step * g_chist[1 * MM + r];
        acoef[2][idx] = step * g_chist[2 * MM + r];
        acoef[3][idx] = step * g_chist[3 * MM + r];
    }
    __syncthreads();

    const int tx = t & 15;
    const int ty = t >> 4;
    const int a_row  = t >> 2;
    const int a_kseg = (t & 3) << 2;
    const int b_row  = t >> 2;
    const int b_kseg = (t & 3) << 2;

    const int r0l = a_row, r1l = a_row + 64;
    const float c00 = acoef[0][r0l], c01 = acoef[1][r0l], c02 = acoef[2][r0l], c03 = acoef[3][r0l];
    const float c10 = acoef[0][r1l], c11 = acoef[1][r1l], c12 = acoef[2][r1l], c13 = acoef[3][r1l];
    const float ri0 = rinv_s[r0l], ri1 = rinv_s[r1l];
    const int gr0 = bm + r0l, gr1 = bm + r1l;

    float acc[8][4];
#pragma unroll
    for (int i = 0; i < 8; i++)
#pragma unroll
        for (int j = 0; j < 4; j++) acc[i][j] = 0.f;

    float4 ra0, ra1, rb;

    auto loadA = [&](int c, float4& o0, float4& o1) {
        int col = c * TBK + a_kseg;
        float4 a0 = *(const float4*)(Cb + (size_t)gr0 * NN + col);
        float4 a1 = *(const float4*)(Cb + (size_t)gr1 * NN + col);
        int jl = col - jbase;
        float aa0[4] = {a0.x, a0.y, a0.z, a0.w};
        float aa1[4] = {a1.x, a1.y, a1.z, a1.w};
        float oo0[4], oo1[4];
#pragma unroll
        for (int q = 0; q < 4; q++) {
            float h0 = chs_s[0][jl + q], h1 = chs_s[1][jl + q];
            float h2 = chs_s[2][jl + q], h3 = chs_s[3][jl + q];
            float m0 = 1.f + c00 * h0 + c01 * h1 + c02 * h2 + c03 * h3;
            float m1 = 1.f + c10 * h0 + c11 * h1 + c12 * h2 + c13 * h3;
            oo0[q] = (col + q <= gr0) ? __expf(aa0[q] * m0) * ri0 : 0.f;
            oo1[q] = (col + q <= gr1) ? __expf(aa1[q] * m1) * ri1 : 0.f;
        }
        o0.x = oo0[0]; o0.y = oo0[1]; o0.z = oo0[2]; o0.w = oo0[3];
        o1.x = oo1[0]; o1.y = oo1[1]; o1.z = oo1[2]; o1.w = oo1[3];
    };

    loadA(c0, ra0, ra1);
    rb = *(const float4*)(VTb + (size_t)b_row * NN + c0 * TBK + b_kseg);

    As[0][a_kseg+0][a_row] = ra0.x; As[0][a_kseg+1][a_row] = ra0.y;
    As[0][a_kseg+2][a_row] = ra0.z; As[0][a_kseg+3][a_row] = ra0.w;
    As[0][a_kseg+0][a_row+64] = ra1.x; As[0][a_kseg+1][a_row+64] = ra1.y;
    As[0][a_kseg+2][a_row+64] = ra1.z; As[0][a_kseg+3][a_row+64] = ra1.w;
    Bs[0][b_kseg+0][b_row] = rb.x; Bs[0][b_kseg+1][b_row] = rb.y;
    Bs[0][b_kseg+2][b_row] = rb.z; Bs[0][b_kseg+3][b_row] = rb.w;
    __syncthreads();

    int buf = 0;
    for (int c = c0; c < c1; c++) {
        if (c + 1 < c1) {
            loadA(c + 1, ra0, ra1);
            rb = *(const float4*)(VTb + (size_t)b_row * NN + (c + 1) * TBK + b_kseg);
        }
#pragma unroll
        for (int k = 0; k < TBK; k++) {
            float4 a0 = *(const float4*)&As[buf][k][ty * 8];
            float4 a1 = *(const float4*)&As[buf][k][ty * 8 + 4];
            float4 b0 = *(const float4*)&Bs[buf][k][tx * 4];
            float av[8] = {a0.x, a0.y, a0.z, a0.w, a1.x, a1.y, a1.z, a1.w};
            float bv[4] = {b0.x, b0.y, b0.z, b0.w};
#pragma unroll
            for (int i = 0; i < 8; i++)
#pragma unroll
                for (int j = 0; j < 4; j++)
                    acc[i][j] = fmaf(av[i], bv[j], acc[i][j]);
        }
        if (c + 1 < c1) {
            int nb = buf ^ 1;
            As[nb][a_kseg+0][a_row] = ra0.x; As[nb][a_kseg+1][a_row] = ra0.y;
            As[nb][a_kseg+2][a_row] = ra0.z; As[nb][a_kseg+3][a_row] = ra0.w;
            As[nb][a_kseg+0][a_row+64] = ra1.x; As[nb][a_kseg+1][a_row+64] = ra1.y;
            As[nb][a_kseg+2][a_row+64] = ra1.z; As[nb][a_kseg+3][a_row+64] = ra1.w;
            Bs[nb][b_kseg+0][b_row] = rb.x; Bs[nb][b_kseg+1][b_row] = rb.y;
            Bs[nb][b_kseg+2][b_row] = rb.z; Bs[nb][b_kseg+3][b_row] = rb.w;
            __syncthreads();
            buf = nb;
        }
    }

#pragma unroll
    for (int i = 0; i < 8; i++) {
        size_t row = (size_t)b * NN + bm + ty * 8 + i;
        int col = tx * 4;
#pragma unroll
        for (int j = 0; j < 4; j++)
            atomicAdd(&g_out64[row * DK + col + j], acc[i][j]);
    }
}

// ---------------- V transpose: g_VT[b][d][j] = g_V[b][j][d] -----------------
__global__ void transpose_v_kernel()
{
    __shared__ float tile[32][33];
    int b = blockIdx.z;
    int j0 = blockIdx.x * 32;
    int d0 = blockIdx.y * 32;
    int x = threadIdx.x, y = threadIdx.y;   // 32 x 8
    const float* Vb = g_V + (size_t)b * NN * DK;
    float* VTb = g_VT + (size_t)b * DK * NN;
#pragma unroll
    for (int yy = y; yy < 32; yy += 8)
        tile[yy][x] = Vb[(size_t)(j0 + yy) * DK + d0 + x];
    __syncthreads();
#pragma unroll
    for (int yy = y; yy < 32; yy += 8)
        VTb[(size_t)(d0 + yy) * NN + j0 + x] = tile[x][yy];
}

__global__ void zero_out64_kernel()
{
    int idx = blockIdx.x * 1024 + threadIdx.x;
    g_out64[idx] = 0.f;
}

// ---------------- features / Q / K / charge from h -----------------
__global__ void feat_qk_kernel(const float* __restrict__ w2, const float* __restrict__ b2,
                               const float* __restrict__ wq, const float* __restrict__ wk,
                               const float* __restrict__ wc, const float* __restrict__ bc)
{
    __shared__ float w2T[H1 * FF];
    __shared__ float wqT[FF * DK];
    __shared__ float wkT[FF * DK];
    __shared__ float wcs[FF];
    __shared__ float b2s[FF];
    __shared__ float hrow[8 * H1];
    __shared__ float feats[8 * FF];

    int tid = threadIdx.x;
    for (int idx = tid; idx < FF * H1; idx += 256) {
        int f = idx / H1, k = idx % H1;
        w2T[k * FF + f] = w2[idx];
    }
    for (int idx = tid; idx < DK * FF; idx += 256) {
        int d = idx / FF, f = idx % FF;
        wqT[f * DK + d] = wq[idx];
        wkT[f * DK + d] = wk[idx];
    }
    if (tid < FF) { wcs[tid] = wc[tid]; b2s[tid] = b2[tid]; }
    __syncthreads();

    int w = tid >> 5, lane = tid & 31;
    int g = blockIdx.x * 8 + w;
    const float* hr = g_h + (size_t)g * H1;
    hrow[w * H1 + lane      ] = hr[lane];
    hrow[w * H1 + lane + 32 ] = hr[lane + 32];
    hrow[w * H1 + lane + 64 ] = hr[lane + 64];
    hrow[w * H1 + lane + 96 ] = hr[lane + 96];
    __syncwarp();

    if (lane < FF) {
        float acc = b2s[lane];
#pragma unroll 4
        for (int k = 0; k < H1; k++)
            acc = fmaf(hrow[w * H1 + k], w2T[k * FF + lane], acc);
        feats[w * FF + lane] = 1.f / (1.f + expf(-acc));
    }
    __syncwarp();

    if (lane == 0) {
        float cc = bc[0];
        for (int f = 0; f < FF; f++) cc += feats[w * FF + f] * wcs[f];
        g_charge[g] = 1.f / (1.f + expf(-cc));
    }

#pragma unroll
    for (int dd = 0; dd < 2; dd++) {
        int d = lane + dd * 32;
        float q = 0.f, kk = 0.f;
#pragma unroll
        for (int f = 0; f < FF; f++) {
            float fv = feats[w * FF + f];
            q  = fmaf(fv, wqT[f * DK + d], q);
            kk = fmaf(fv, wkT[f * DK + d], kk);
        }
        g_Q[(size_t)g * DK + d] = q;
        g_K[(size_t)g * DK + d] = kk;
    }
}

// ---------------- softmax pass t: 8 rows/block, no-max, __expf, column sums ----------
#define PROWS 8
__global__ void softmax_pass_kernel(int nterms, const float* __restrict__ step_ptr)
{
    extern __shared__ float sm[];
    float* rowbuf = sm;                    // PROWS*NN
    float* chs    = sm + PROWS * NN;       // 4*NN (only j < r0+PROWS loaded)
    float* invs   = chs + 4 * NN;          // PROWS

    int b = blockIdx.y, r0 = blockIdx.x * PROWS;
    int tid = threadIdx.x, w = tid >> 5, lane = tid & 31;
    float step = *step_ptr;
    int jlim = r0 + PROWS;

    for (int s = 0; s < nterms; s++)
        for (int j = tid; j < jlim; j += 256)
            chs[s * NN + j] = g_chist[s * MM + b * NN + j];
    __syncthreads();

    int i = r0 + w;
    int len = i + 1;
    const float* crow = g_compat + ((size_t)b * NN + i) * NN;
    float* rb = rowbuf + w * NN;

    float a0 = 0.f, a1 = 0.f, a2 = 0.f, a3 = 0.f;
    if (nterms > 0) a0 = step * chs[i];
    if (nterms > 1) a1 = step * chs[NN + i];
    if (nterms > 2) a2 = step * chs[2 * NN + i];
    if (nterms > 3) a3 = step * chs[3 * NN + i];

    float s = 0.f;
    for (int j = lane; j < len; j += 32) {
        float m = 1.f;
        if (nterms > 0) m = fmaf(a0, chs[j], m);
        if (nterms > 1) m = fmaf(a1, chs[NN + j], m);
        if (nterms > 2) m = fmaf(a2, chs[2 * NN + j], m);
        if (nterms > 3) m = fmaf(a3, chs[3 * NN + j], m);
        float e = __expf(crow[j] * m);
        rb[j] = e;
        s += e;
    }
#pragma unroll
    for (int o = 16; o; o >>= 1) s += __shfl_xor_sync(0xffffffffu, s, o);
    if (lane == 0) invs[w] = 1.f / s;
    __syncthreads();

    int jmax = jlim; if (jmax > NN) jmax = NN;
    for (int j = tid; j < jmax; j += 256) {
        float acc = 0.f;
        int wstart = (j > r0) ? (j - r0) : 0;
        for (int ww = wstart; ww < PROWS; ww++)
            acc += rowbuf[ww * NN + j] * invs[ww];
        atomicAdd(&g_recv[b * NN + j], acc);
    }
}

// ---------------- row sums of final exp (no materialization) -----------------
__global__ void rowsum_kernel(const float* __restrict__ step_ptr)
{
    __shared__ float chs[4 * NN];
    int b = blockIdx.y, r0 = blockIdx.x * PROWS;
    int tid = threadIdx.x, w = tid >> 5, lane = tid & 31;
    float step = *step_ptr;
    int jlim = r0 + PROWS;

    for (int s = 0; s < 4; s++)
        for (int j = tid; j < jlim; j += 256)
            chs[s * NN + j] = g_chist[s * MM + b * NN + j];
    __syncthreads();

    int i = r0 + w;
    int len = i + 1;
    const float* crow = g_compat + ((size_t)b * NN + i) * NN;

    float a0 = step * chs[i];
    float a1 = step * chs[NN + i];
    float a2 = step * chs[2 * NN + i];
    float a3 = step * chs[3 * NN + i];

    float s = 0.f;
    for (int j = lane; j < len; j += 32) {
        float m = 1.f;
        m = fmaf(a0, chs[j], m);
        m = fmaf(a1, chs[NN + j], m);
        m = fmaf(a2, chs[2 * NN + j], m);
        m = fmaf(a3, chs[3 * NN + j], m);
        s += __expf(crow[j] * m);
    }
#pragma unroll
    for (int o = 16; o; o >>= 1) s += __shfl_xor_sync(0xffffffffu, s, o);
    if (lane == 0) g_rowinv[b * NN + i] = 1.f / s;
}

// ---------------- charge update + recv re-zero -----------------
__global__ void charge_update_kernel(int t, const float* __restrict__ decay_ptr)
{
    int idx = blockIdx.x * 256 + threadIdx.x;
    float r = g_recv[idx];
    g_recv[idx] = 0.f;
    float d = *decay_ptr;
    float sg = 1.f / (1.f + expf(-(r - 1.f)));
    float c = g_charge[idx] * (1.f - d * sg);
    g_charge[idx] = c;
    g_chist[t * MM + idx] = c;
}

// =====================================================================================
extern "C" void kernel_launch(void* const* d_in, const int* in_sizes, int n_in,
                              void* d_out, int out_size)
{
    const float* hs      = (const float*)d_in[0];
    const float* w1      = (const float*)d_in[2];
    const float* b1      = (const float*)d_in[3];
    const float* w2      = (const float*)d_in[4];
    const float* b2      = (const float*)d_in[5];
    const float* wq      = (const float*)d_in[6];
    const float* wk      = (const float*)d_in[7];
    const float* wc      = (const float*)d_in[8];
    const float* bc      = (const float*)d_in[9];
    const float* step_p  = (const float*)d_in[10];
    const float* decay_p = (const float*)d_in[11];
    const float* wv      = (const float*)d_in[12];
    const float* wo      = (const float*)d_in[13];
    const float* alpha_p = (const float*)d_in[14];
    float* out = (float*)d_out;

    float *ph, *pV, *pC;
    __nv_bfloat16 *p_hsh, *p_hsl, *p_w1h, *p_w1l, *p_wvh, *p_wvl, *p_woh, *p_wol;
    __nv_bfloat16 *p_Qh, *p_Ql, *p_Kh, *p_Kl, *p_oh, *p_ol;
    cudaGetSymbolAddress((void**)&ph,    g_h);
    cudaGetSymbolAddress((void**)&pV,    g_V);
    cudaGetSymbolAddress((void**)&pC,    g_compat);
    cudaGetSymbolAddress((void**)&p_hsh, g_hs_hi);
    cudaGetSymbolAddress((void**)&p_hsl, g_hs_lo);
    cudaGetSymbolAddress((void**)&p_w1h, g_w1_hi);
    cudaGetSymbolAddress((void**)&p_w1l, g_w1_lo);
    cudaGetSymbolAddress((void**)&p_wvh, g_wv_hi);
    cudaGetSymbolAddress((void**)&p_wvl, g_wv_lo);
    cudaGetSymbolAddress((void**)&p_woh, g_wo_hi);
    cudaGetSymbolAddress((void**)&p_wol, g_wo_lo);
    cudaGetSymbolAddress((void**)&p_Qh,  g_Q_hi);
    cudaGetSymbolAddress((void**)&p_Ql,  g_Q_lo);
    cudaGetSymbolAddress((void**)&p_Kh,  g_K_hi);
    cudaGetSymbolAddress((void**)&p_Kl,  g_K_lo);
    cudaGetSymbolAddress((void**)&p_oh,  g_o64_hi);
    cudaGetSymbolAddress((void**)&p_ol,  g_o64_lo);

    const int smem_pass = (PROWS * NN + 4 * NN + PROWS) * 4;
    cudaFuncSetAttribute(softmax_pass_kernel,
                         cudaFuncAttributeMaxDynamicSharedMemorySize, smem_pass);
    cudaFuncSetAttribute(mma_gemm_kernel<EPI_GELU_BIAS,false>,
                         cudaFuncAttributeMaxDynamicSharedMemorySize, G_SMEM);
    cudaFuncSetAttribute(mma_gemm_kernel<EPI_NONE,false>,
                         cudaFuncAttributeMaxDynamicSharedMemorySize, G_SMEM);
    cudaFuncSetAttribute(mma_gemm_kernel<EPI_SCALE,true>,
                         cudaFuncAttributeMaxDynamicSharedMemorySize, G_SMEM);
    cudaFuncSetAttribute(mma_gemm_kernel<EPI_ALPHA,false>,
                         cudaFuncAttributeMaxDynamicSharedMemorySize, G_SMEM);

    // 1,2) split hs and w1 into bf16 hi/lo
    cvt_split_kernel<<<(MM * DD) / 256, 256>>>(hs, p_hsh, p_hsl, MM * DD);
    cvt_split_kernel<<<(H1 * DD) / 256, 256>>>(w1, p_w1h, p_w1l, H1 * DD);

    // 3) h = gelu(hs @ w1^T + b1)    [HMMA]
    mma_gemm_kernel<EPI_GELU_BIAS,false><<<dim3(H1/64, MM/128, 1), 256, G_SMEM>>>(
        p_hsh, p_hsl, p_w1h, p_w1l, b1, ph, H1, DD, 0, 0, 0, nullptr);

    // 4) features -> Q, K, charge0
    feat_qk_kernel<<<MM / 8, 256>>>(w2, b2, wq, wk, wc, bc);

    // 5) split Q, K
    cvt_split_qk_kernel<<<(MM * DK) / 256, 256>>>();

    // 6) compat = Q @ K^T / 8 (triangular tile set)    [HMMA]  <- profiled slot
    mma_gemm_kernel<EPI_SCALE,true><<<dim3(NN/64, NN/128, BB), 256, G_SMEM>>>(
        p_Qh, p_Ql, p_Kh, p_Kl, nullptr, pC, NN, DK,
        (size_t)NN*DK, (size_t)NN*DK, (size_t)NN*NN, nullptr);

    // 7,8) V = hs @ wv^T    [HMMA]
    cvt_split_kernel<<<(DK * DD) / 256, 256>>>(wv, p_wvh, p_wvl, DK * DD);
    mma_gemm_kernel<EPI_NONE,false><<<dim3(DK/64, MM/128, 1), 256, G_SMEM>>>(
        p_hsh, p_hsl, p_wvh, p_wvl, nullptr, pV, DK, DD, 0, 0, 0, nullptr);

    // 9) VT[b][d][j] = V[b][j][d]
    transpose_v_kernel<<<dim3(NN/32, DK/32, BB), dim3(32, 8)>>>();

    // 10) 4 charge iterations
    for (int t = 0; t < NSTEPS; t++) {
        softmax_pass_kernel<<<dim3(NN/PROWS, BB), 256, smem_pass>>>(t, step_p);
        charge_update_kernel<<<MM/256, 256>>>(t, decay_p);
    }

    // 11) row sums of final softmax
    rowsum_kernel<<<dim3(NN/PROWS, BB), 256>>>(step_p);

    // 12) out64 = softmax(logits) @ V, exp fused, split-K=4
    zero_out64_kernel<<<(MM*DK)/1024, 1024>>>();
    attn_v_fused_kernel<<<dim3(4, NN/TBM, BB), 256>>>(step_p);

    // 13) split out64 and wo
    cvt_split_o64_kernel<<<(MM * DK) / 256, 256>>>();
    cvt_split_kernel<<<(DD * DK) / 256, 256>>>(wo, p_woh, p_wol, DD * DK);

    // 14) out = alpha * (out64 @ wo^T)    [HMMA]
    mma_gemm_kernel<EPI_ALPHA,false><<<dim3(DD/64, MM/128, 1), 256, G_SMEM>>>(
        p_oh, p_ol, p_woh, p_wol, nullptr, out, DD, DK, 0, 0, 0, alpha_p);
}